// round 6
// baseline (speedup 1.0000x reference)
#include <cuda_runtime.h>
#include <math.h>

// ---------------------------------------------------------------------------
// Problem constants
// ---------------------------------------------------------------------------
#define BB      2
#define NVIEW   6
#define DIMC    128
#define HWQ     1024          // 32*32
#define HWK     1680          // 28*60
#define HEADS   4
#define DH      32
#define INNER   128
#define ROWS_Q  (BB*NVIEW*HWQ)   // 12288
#define ROWS_K  (BB*NVIEW*HWK)   // 20160
#define ROWS_Z  (BB*HWQ)         // 2048
#define ATTN_SCALE 0.17677669529663687f  // 1/sqrt(32)

// Attention tiling
#define TQ    16               // queries per block
#define KC    48               // keys per chunk (1680 = 35*48)
#define KSTR  36               // padded row stride Ks/Vs (floats)
#define PSTR  52               // padded row stride Ps (floats)
#define NCHUNK 210             // 6 views * 35 chunks

// ---------------------------------------------------------------------------
// Scratch (static device memory — no allocations anywhere)
// ---------------------------------------------------------------------------
__device__ float d_qp [ROWS_Q * DIMC];
__device__ float d_kp [ROWS_K * DIMC];
__device__ float d_vp [ROWS_K * DIMC];
__device__ float d_aout[ROWS_Z * DIMC];
__device__ float d_z1 [ROWS_Z * DIMC];
__device__ float d_zn [ROWS_Z * DIMC];
__device__ float d_hh [ROWS_Z * 256];
__device__ float d_m2 [ROWS_Z * DIMC];

// ---------------------------------------------------------------------------
// Kernel 1: fused LayerNorm + projection GEMM.
// C[M][128] = LN(x_row) @ W[128][128]^T + bias, x in CHW layout:
// x[(slab*128 + d)*HW + p], global row = slab*HW + p.
// Block: 64 rows x 64 cols, 256 threads.
// ---------------------------------------------------------------------------
__global__ __launch_bounds__(256)
void gemm_ln_kernel(const float* __restrict__ x,
                    const float* __restrict__ g, const float* __restrict__ bt,
                    const float* __restrict__ W, const float* __restrict__ bias,
                    float* __restrict__ C, int HW) {
    __shared__ float As[64 * 132];
    __shared__ __align__(16) float Bs[16 * 68];
    __shared__ float rowm[64], rowr[64];

    const int tid = threadIdx.x;
    const int tx  = tid & 15;
    const int ty  = tid >> 4;
    const int m0  = blockIdx.y * 64;
    const int n0  = blockIdx.x * 64;

    // ---- stage raw A tile: coalesced in p (64 consecutive rows) ----
    {
        const int rr = tid & 63;
        int slab = m0 / HW;
        int p    = m0 - slab * HW + rr;
        if (p >= HW) { p -= HW; slab++; }
        const float* src = x + ((size_t)slab * DIMC) * HW + p;
        const int dbase = tid >> 6;                  // 0..3
        #pragma unroll
        for (int i = 0; i < 32; ++i) {
            int d = dbase + i * 4;
            As[rr * 132 + d] = src[(size_t)d * HW];
        }
    }
    __syncthreads();

    // ---- row stats: 4 threads per row, strided elements ----
    {
        const int r  = tid >> 2;
        const int qd = tid & 3;
        float s = 0.f, ss = 0.f;
        #pragma unroll
        for (int j = 0; j < 32; ++j) {
            float v = As[r * 132 + qd + 4 * j];
            s += v; ss += v * v;
        }
        s  += __shfl_xor_sync(0xffffffffu, s, 1);
        ss += __shfl_xor_sync(0xffffffffu, ss, 1);
        s  += __shfl_xor_sync(0xffffffffu, s, 2);
        ss += __shfl_xor_sync(0xffffffffu, ss, 2);
        if (qd == 0) {
            float mean = s * (1.f / 128.f);
            rowm[r] = mean;
            rowr[r] = rsqrtf(ss * (1.f / 128.f) - mean * mean + 1e-5f);
        }
    }
    __syncthreads();

    // ---- normalize in place with gamma/beta ----
    {
        const int rr = tid & 63;
        const int dbase = tid >> 6;
        float mean = rowm[rr], rstd = rowr[rr];
        #pragma unroll
        for (int i = 0; i < 32; ++i) {
            int d = dbase + i * 4;
            float v = As[rr * 132 + d];
            As[rr * 132 + d] = (v - mean) * rstd * g[d] + bt[d];
        }
    }
    __syncthreads();

    // ---- GEMM: 8 k-tiles of 16 ----
    float acc[4][4] = {};
    for (int kt = 0; kt < 128; kt += 16) {
        #pragma unroll
        for (int e = tid; e < 16 * 64; e += 256) {
            int k = e & 15, n = e >> 4;
            Bs[k * 68 + n] = W[(n0 + n) * 128 + kt + k];
        }
        __syncthreads();
        #pragma unroll
        for (int kk = 0; kk < 16; ++kk) {
            float a0 = As[(ty * 4 + 0) * 132 + kt + kk];
            float a1 = As[(ty * 4 + 1) * 132 + kt + kk];
            float a2 = As[(ty * 4 + 2) * 132 + kt + kk];
            float a3 = As[(ty * 4 + 3) * 132 + kt + kk];
            float4 bv = *reinterpret_cast<const float4*>(&Bs[kk * 68 + tx * 4]);
            acc[0][0] += a0 * bv.x; acc[0][1] += a0 * bv.y; acc[0][2] += a0 * bv.z; acc[0][3] += a0 * bv.w;
            acc[1][0] += a1 * bv.x; acc[1][1] += a1 * bv.y; acc[1][2] += a1 * bv.z; acc[1][3] += a1 * bv.w;
            acc[2][0] += a2 * bv.x; acc[2][1] += a2 * bv.y; acc[2][2] += a2 * bv.z; acc[2][3] += a2 * bv.w;
            acc[3][0] += a3 * bv.x; acc[3][1] += a3 * bv.y; acc[3][2] += a3 * bv.z; acc[3][3] += a3 * bv.w;
        }
        __syncthreads();
    }

    #pragma unroll
    for (int i = 0; i < 4; ++i) {
        int row = m0 + ty * 4 + i;
        #pragma unroll
        for (int j = 0; j < 4; ++j) {
            int col = n0 + tx * 4 + j;
            C[(size_t)row * 128 + col] = acc[i][j] + bias[col];
        }
    }
}

// ---------------------------------------------------------------------------
// Kernel 2: plain GEMM + bias (+ optional exact GELU), row-major A.
// ---------------------------------------------------------------------------
template<bool GELU>
__global__ __launch_bounds__(256)
void gemm_bias_kernel(const float* __restrict__ A, const float* __restrict__ W,
                      const float* __restrict__ bias, float* __restrict__ C,
                      int M, int N, int K) {
    __shared__ __align__(16) float As[64 * 17];
    __shared__ __align__(16) float Bs[16 * 68];

    const int tid = threadIdx.x;
    const int tx  = tid & 15;
    const int ty  = tid >> 4;
    const int m0  = blockIdx.y * 64;
    const int n0  = blockIdx.x * 64;

    float acc[4][4] = {};

    for (int kt = 0; kt < K; kt += 16) {
        #pragma unroll
        for (int e = tid; e < 64 * 16; e += 256) {
            int r = e >> 4, k = e & 15;
            As[r * 17 + k] = A[(m0 + r) * K + kt + k];
        }
        #pragma unroll
        for (int e = tid; e < 16 * 64; e += 256) {
            int k = e & 15, n = e >> 4;
            Bs[k * 68 + n] = W[(n0 + n) * K + kt + k];
        }
        __syncthreads();
        #pragma unroll
        for (int kk = 0; kk < 16; ++kk) {
            float a0 = As[(ty * 4 + 0) * 17 + kk];
            float a1 = As[(ty * 4 + 1) * 17 + kk];
            float a2 = As[(ty * 4 + 2) * 17 + kk];
            float a3 = As[(ty * 4 + 3) * 17 + kk];
            float4 bv = *reinterpret_cast<const float4*>(&Bs[kk * 68 + tx * 4]);
            acc[0][0] += a0 * bv.x; acc[0][1] += a0 * bv.y; acc[0][2] += a0 * bv.z; acc[0][3] += a0 * bv.w;
            acc[1][0] += a1 * bv.x; acc[1][1] += a1 * bv.y; acc[1][2] += a1 * bv.z; acc[1][3] += a1 * bv.w;
            acc[2][0] += a2 * bv.x; acc[2][1] += a2 * bv.y; acc[2][2] += a2 * bv.z; acc[2][3] += a2 * bv.w;
            acc[3][0] += a3 * bv.x; acc[3][1] += a3 * bv.y; acc[3][2] += a3 * bv.z; acc[3][3] += a3 * bv.w;
        }
        __syncthreads();
    }

    #pragma unroll
    for (int i = 0; i < 4; ++i) {
        int row = m0 + ty * 4 + i;
        #pragma unroll
        for (int j = 0; j < 4; ++j) {
            int col = n0 + tx * 4 + j;
            float v = acc[i][j] + bias[col];
            if (GELU) v = 0.5f * v * (1.f + erff(v * 0.70710678118654752f));
            C[row * N + col] = v;
        }
    }
}

// ---------------------------------------------------------------------------
// Kernel 3: flash attention, 256 threads, double-buffered K/V staging.
// Block = 16 queries x (head, batch); 210 chunks of 48 keys.
// Per-thread: q = tid>>4 (one query), t16 = tid&15.
//   S phase : keys t16*3 .. t16*3+2
//   softmax : logits t16 + 16*i
//   AV      : dims t16*2, t16*2+1
// ---------------------------------------------------------------------------
__global__ __launch_bounds__(256)
void attn_kernel(const float* __restrict__ qp, const float* __restrict__ kp,
                 const float* __restrict__ vp, float* __restrict__ aout) {
    const int qt = blockIdx.x, m = blockIdx.y, b = blockIdx.z;
    const int q0 = qt * TQ;
    const int tid = threadIdx.x;

    __shared__ __align__(16) float qs[TQ * NVIEW * DH];      // 3072
    __shared__ __align__(16) float Ks[2][KC * KSTR];         // 2 x 1728
    __shared__ __align__(16) float Vs[2][KC * KSTR];
    __shared__ __align__(16) float Ps[TQ * PSTR];            // 832

    // ---- stage queries: 768 float4 entries, 3 per thread ----
    {
        const float* qbase = qp + ((size_t)b * NVIEW * HWQ) * DIMC + m * DH;
        #pragma unroll
        for (int r = 0; r < 3; ++r) {
            int e  = tid + r * 256;
            int d4 = e & 7;
            int nn = (e >> 3) % 6;
            int qq = e / 48;
            *reinterpret_cast<float4*>(&qs[(qq * 6 + nn) * DH + d4 * 4]) =
                *reinterpret_cast<const float4*>(
                    &qbase[((size_t)nn * HWQ + q0 + qq) * DIMC + d4 * 4]);
        }
    }

    const int q   = tid >> 4;
    const int t16 = tid & 15;

    // staging decomposition (same for prologue / prefetch / STS)
    int srow[3], sd4[3], sarr[3];
    #pragma unroll
    for (int r = 0; r < 3; ++r) {
        int e   = tid + r * 256;           // 0..767
        sarr[r] = (e >= 384);
        int idx = e - (sarr[r] ? 384 : 0); // 0..383
        srow[r] = idx >> 3;                // 0..47
        sd4[r]  = idx & 7;
    }
    const size_t kvhead = ((size_t)b * NVIEW * HWK) * DIMC + m * DH;
    const float* kbase = kp + kvhead;
    const float* vbase = vp + kvhead;

    // ---- prologue: chunk 0 into buffer 0 ----
    #pragma unroll
    for (int r = 0; r < 3; ++r) {
        const float* src = sarr[r] ? vbase : kbase;
        float4 v = *reinterpret_cast<const float4*>(
            &src[(size_t)srow[r] * DIMC + sd4[r] * 4]);
        (sarr[r] ? Vs : Ks)[0][srow[r] * KSTR + sd4[r] * 4] = v.x;
        *reinterpret_cast<float4*>(
            &(sarr[r] ? Vs : Ks)[0][srow[r] * KSTR + sd4[r] * 4]) = v;
    }
    __syncthreads();

    float o0 = 0.f, o1 = 0.f;
    float mrun = -INFINITY, lrun = 0.f;
    float4 pf0, pf1, pf2;

    for (int ci = 0; ci < NCHUNK; ++ci) {
        const int cur = ci & 1;
        const int nn  = ci / 35;
        const bool more = (ci + 1 < NCHUNK);

        // ---- prefetch next chunk into registers (latency overlapped) ----
        if (more) {
            int ci2 = ci + 1;
            int nn2 = ci2 / 35;
            int cc2 = ci2 - nn2 * 35;
            size_t base2 = ((size_t)nn2 * HWK + cc2 * KC) * DIMC;
            pf0 = *reinterpret_cast<const float4*>(
                &(sarr[0] ? vbase : kbase)[base2 + (size_t)srow[0] * DIMC + sd4[0] * 4]);
            pf1 = *reinterpret_cast<const float4*>(
                &(sarr[1] ? vbase : kbase)[base2 + (size_t)srow[1] * DIMC + sd4[1] * 4]);
            pf2 = *reinterpret_cast<const float4*>(
                &(sarr[2] ? vbase : kbase)[base2 + (size_t)srow[2] * DIMC + sd4[2] * 4]);
        }

        // ---- S = Q K^T : 1 query x 3 keys per thread ----
        {
            const float* qrow = &qs[(q * 6 + nn) * DH];
            const float* krow = &Ks[cur][(t16 * 3) * KSTR];
            float a0 = 0.f, a1 = 0.f, a2 = 0.f;
            #pragma unroll
            for (int d4 = 0; d4 < 8; ++d4) {
                float4 qv = *reinterpret_cast<const float4*>(&qrow[d4 * 4]);
                float4 k0 = *reinterpret_cast<const float4*>(&krow[0 * KSTR + d4 * 4]);
                float4 k1 = *reinterpret_cast<const float4*>(&krow[1 * KSTR + d4 * 4]);
                float4 k2 = *reinterpret_cast<const float4*>(&krow[2 * KSTR + d4 * 4]);
                a0 += qv.x * k0.x + qv.y * k0.y + qv.z * k0.z + qv.w * k0.w;
                a1 += qv.x * k1.x + qv.y * k1.y + qv.z * k1.z + qv.w * k1.w;
                a2 += qv.x * k2.x + qv.y * k2.y + qv.z * k2.z + qv.w * k2.w;
            }
            Ps[q * PSTR + t16 * 3 + 0] = a0 * ATTN_SCALE;
            Ps[q * PSTR + t16 * 3 + 1] = a1 * ATTN_SCALE;
            Ps[q * PSTR + t16 * 3 + 2] = a2 * ATTN_SCALE;
        }
        __syncthreads();

        // ---- online softmax (16-thread groups) ----
        {
            float s0 = Ps[q * PSTR + t16];
            float s1 = Ps[q * PSTR + t16 + 16];
            float s2 = Ps[q * PSTR + t16 + 32];
            float cmax = fmaxf(s0, fmaxf(s1, s2));
            #pragma unroll
            for (int o = 8; o; o >>= 1)
                cmax = fmaxf(cmax, __shfl_xor_sync(0xffffffffu, cmax, o));
            float mnew = fmaxf(mrun, cmax);
            float e0 = __expf(s0 - mnew);
            float e1 = __expf(s1 - mnew);
            float e2 = __expf(s2 - mnew);
            Ps[q * PSTR + t16]      = e0;
            Ps[q * PSTR + t16 + 16] = e1;
            Ps[q * PSTR + t16 + 32] = e2;
            float lsum = e0 + e1 + e2;
            #pragma unroll
            for (int o = 8; o; o >>= 1)
                lsum += __shfl_xor_sync(0xffffffffu, lsum, o);
            float alpha = __expf(mrun - mnew);
            lrun = lrun * alpha + lsum;
            mrun = mnew;
            o0 *= alpha; o1 *= alpha;
        }
        __syncwarp();

        // ---- O += P V : 1 query x 2 dims per thread ----
        {
            const float* prow = &Ps[q * PSTR];
            const float* vrow = &Vs[cur][t16 * 2];
            #pragma unroll
            for (int j4 = 0; j4 < KC / 4; ++j4) {
                float4 pv = *reinterpret_cast<const float4*>(&prow[j4 * 4]);
                float2 v0 = *reinterpret_cast<const float2*>(&vrow[(j4 * 4 + 0) * KSTR]);
                float2 v1 = *reinterpret_cast<const float2*>(&vrow[(j4 * 4 + 1) * KSTR]);
                float2 v2 = *reinterpret_cast<const float2*>(&vrow[(j4 * 4 + 2) * KSTR]);
                float2 v3 = *reinterpret_cast<const float2*>(&vrow[(j4 * 4 + 3) * KSTR]);
                o0 += pv.x * v0.x + pv.y * v1.x + pv.z * v2.x + pv.w * v3.x;
                o1 += pv.x * v0.y + pv.y * v1.y + pv.z * v2.y + pv.w * v3.y;
            }
        }

        // ---- commit prefetched chunk into the other buffer ----
        if (more) {
            const int nxt = cur ^ 1;
            *reinterpret_cast<float4*>(
                &(sarr[0] ? Vs : Ks)[nxt][srow[0] * KSTR + sd4[0] * 4]) = pf0;
            *reinterpret_cast<float4*>(
                &(sarr[1] ? Vs : Ks)[nxt][srow[1] * KSTR + sd4[1] * 4]) = pf1;
            *reinterpret_cast<float4*>(
                &(sarr[2] ? Vs : Ks)[nxt][srow[2] * KSTR + sd4[2] * 4]) = pf2;
        }
        __syncthreads();
    }

    float inv = 1.f / lrun;
    float2 outv = make_float2(o0 * inv, o1 * inv);
    *reinterpret_cast<float2*>(
        &aout[((size_t)(b * HWQ + q0 + q)) * INNER + m * DH + t16 * 2]) = outv;
}

// ---------------------------------------------------------------------------
// Kernel 4: z = LN1(proj_out + skip(CHW)).
// ---------------------------------------------------------------------------
__global__ void skip_ln_kernel(const float* __restrict__ z1,
                               const float* __restrict__ skip,
                               const float* __restrict__ g,
                               const float* __restrict__ bt,
                               float* __restrict__ zn) {
    int row = blockIdx.x;
    int b = row >> 10, p = row & 1023;
    int d = threadIdx.x;
    float v = z1[row * DIMC + d] + skip[(b * DIMC + d) * HWQ + p];

    float s = v, ss = v * v;
    #pragma unroll
    for (int o = 16; o; o >>= 1) {
        s  += __shfl_xor_sync(0xffffffffu, s,  o);
        ss += __shfl_xor_sync(0xffffffffu, ss, o);
    }
    __shared__ float sh[8];
    int w = d >> 5, l = d & 31;
    if (l == 0) { sh[w] = s; sh[4 + w] = ss; }
    __syncthreads();
    s  = sh[0] + sh[1] + sh[2] + sh[3];
    ss = sh[4] + sh[5] + sh[6] + sh[7];
    float mean = s * (1.f / 128.f);
    float rstd = rsqrtf(ss * (1.f / 128.f) - mean * mean + 1e-5f);
    zn[row * DIMC + d] = (v - mean) * rstd * g[d] + bt[d];
}

// ---------------------------------------------------------------------------
// Kernel 5: out(CHW) = LN2(zn + mlp_out).
// ---------------------------------------------------------------------------
__global__ void final_ln_kernel(const float* __restrict__ zn,
                                const float* __restrict__ m2,
                                const float* __restrict__ g,
                                const float* __restrict__ bt,
                                float* __restrict__ out) {
    int row = blockIdx.x;
    int b = row >> 10, p = row & 1023;
    int d = threadIdx.x;
    float v = zn[row * DIMC + d] + m2[row * DIMC + d];

    float s = v, ss = v * v;
    #pragma unroll
    for (int o = 16; o; o >>= 1) {
        s  += __shfl_xor_sync(0xffffffffu, s,  o);
        ss += __shfl_xor_sync(0xffffffffu, ss, o);
    }
    __shared__ float sh[8];
    int w = d >> 5, l = d & 31;
    if (l == 0) { sh[w] = s; sh[4 + w] = ss; }
    __syncthreads();
    s  = sh[0] + sh[1] + sh[2] + sh[3];
    ss = sh[4] + sh[5] + sh[6] + sh[7];
    float mean = s * (1.f / 128.f);
    float rstd = rsqrtf(ss * (1.f / 128.f) - mean * mean + 1e-5f);
    out[(b * DIMC + d) * HWQ + p] = (v - mean) * rstd * g[d] + bt[d];
}

// ---------------------------------------------------------------------------
// Launcher
// ---------------------------------------------------------------------------
extern "C" void kernel_launch(void* const* d_in, const int* in_sizes, int n_in,
                              void* d_out, int out_size) {
    const float* q     = (const float*)d_in[0];
    const float* k     = (const float*)d_in[1];
    const float* v     = (const float*)d_in[2];
    const float* skip  = (const float*)d_in[3];
    const float* lnq_g = (const float*)d_in[4];
    const float* lnq_b = (const float*)d_in[5];
    const float* Wq    = (const float*)d_in[6];
    const float* bq    = (const float*)d_in[7];
    const float* lnk_g = (const float*)d_in[8];
    const float* lnk_b = (const float*)d_in[9];
    const float* Wk    = (const float*)d_in[10];
    const float* bk    = (const float*)d_in[11];
    const float* lnv_g = (const float*)d_in[12];
    const float* lnv_b = (const float*)d_in[13];
    const float* Wv    = (const float*)d_in[14];
    const float* bv    = (const float*)d_in[15];
    const float* Wp    = (const float*)d_in[16];
    const float* bp    = (const float*)d_in[17];
    const float* ln1_g = (const float*)d_in[18];
    const float* ln1_b = (const float*)d_in[19];
    const float* W1    = (const float*)d_in[20];
    const float* b1    = (const float*)d_in[21];
    const float* W2    = (const float*)d_in[22];
    const float* b2    = (const float*)d_in[23];
    const float* ln2_g = (const float*)d_in[24];
    const float* ln2_b = (const float*)d_in[25];
    float* out = (float*)d_out;

    float *qp, *kp, *vp, *aout, *z1, *zn, *hh, *m2;
    cudaGetSymbolAddress((void**)&qp,   d_qp);
    cudaGetSymbolAddress((void**)&kp,   d_kp);
    cudaGetSymbolAddress((void**)&vp,   d_vp);
    cudaGetSymbolAddress((void**)&aout, d_aout);
    cudaGetSymbolAddress((void**)&z1,   d_z1);
    cudaGetSymbolAddress((void**)&zn,   d_zn);
    cudaGetSymbolAddress((void**)&hh,   d_hh);
    cudaGetSymbolAddress((void**)&m2,   d_m2);

    // 1. Fused LN + projection (CHW gather, coalesced over p)
    gemm_ln_kernel<<<dim3(2, ROWS_Q / 64), 256>>>(q, lnq_g, lnq_b, Wq, bq, qp, HWQ);
    gemm_ln_kernel<<<dim3(2, ROWS_K / 64), 256>>>(k, lnk_g, lnk_b, Wk, bk, kp, HWK);
    gemm_ln_kernel<<<dim3(2, ROWS_K / 64), 256>>>(v, lnv_g, lnv_b, Wv, bv, vp, HWK);

    // 2. Attention (joint softmax over all views)
    attn_kernel<<<dim3(HWQ / TQ, HEADS, BB), 256>>>(qp, kp, vp, aout);

    // 3. Output projection + skip + LN1
    gemm_bias_kernel<false><<<dim3(2, ROWS_Z / 64), 256>>>(aout, Wp, bp, z1, ROWS_Z, 128, 128);
    skip_ln_kernel<<<ROWS_Z, 128>>>(z1, skip, ln1_g, ln1_b, zn);

    // 4. MLP (GELU exact) + residual + LN2 + NCHW output
    gemm_bias_kernel<true ><<<dim3(4, ROWS_Z / 64), 256>>>(zn, W1, b1, hh, ROWS_Z, 256, 128);
    gemm_bias_kernel<false><<<dim3(2, ROWS_Z / 64), 256>>>(hh, W2, b2, m2, ROWS_Z, 128, 256);
    final_ln_kernel<<<ROWS_Z, 128>>>(zn, m2, ln2_g, ln2_b, out);
}

// round 7
// speedup vs baseline: 5.4802x; 5.4802x over previous
#include <cuda_runtime.h>
#include <cuda_bf16.h>
#include <math.h>

// ---------------------------------------------------------------------------
// Problem constants
// ---------------------------------------------------------------------------
#define BB      2
#define NVIEW   6
#define DIMC    128
#define HWQ     1024          // 32*32
#define HWK     1680          // 28*60
#define HEADS   4
#define DH      32
#define INNER   128
#define ROWS_Q  (BB*NVIEW*HWQ)   // 12288
#define ROWS_K  (BB*NVIEW*HWK)   // 20160
#define ROWS_Z  (BB*HWQ)         // 2048
#define ATTN_SCALE 0.17677669529663687f  // 1/sqrt(32)

// Attention (tensor-core) tiling
#define AQT   64               // queries per block (4 warps x 16)
#define AKC   48               // keys per chunk (1680 = 35*48)
#define NCH   35               // chunks per view
#define KVSTR 40               // padded bf16 row stride (80B, ldmatrix conflict-free)
#define NPART (NVIEW*8*16)     // 768 partial tiles

// ---------------------------------------------------------------------------
// Scratch (static device memory — no allocations anywhere)
// ---------------------------------------------------------------------------
__device__ __nv_bfloat16 d_qp [ROWS_Q * DIMC];
__device__ __nv_bfloat16 d_kp [ROWS_K * DIMC];
__device__ __nv_bfloat16 d_vp [ROWS_K * DIMC];
__device__ float d_pO  [NPART * AQT * DH];   // unnormalized partial O
__device__ float d_pml [NPART * AQT * 2];    // running (m, l) per row
__device__ float d_aout[ROWS_Z * DIMC];
__device__ float d_z1 [ROWS_Z * DIMC];
__device__ float d_zn [ROWS_Z * DIMC];
__device__ float d_hh [ROWS_Z * 256];
__device__ float d_m2 [ROWS_Z * DIMC];

// ---------------------------------------------------------------------------
// PTX helpers
// ---------------------------------------------------------------------------
__device__ __forceinline__ void ldsm_x4(unsigned addr, unsigned* r) {
    asm volatile("ldmatrix.sync.aligned.m8n8.x4.shared.b16 {%0,%1,%2,%3}, [%4];"
                 : "=r"(r[0]), "=r"(r[1]), "=r"(r[2]), "=r"(r[3]) : "r"(addr));
}
__device__ __forceinline__ void ldsm_x2(unsigned addr, unsigned& r0, unsigned& r1) {
    asm volatile("ldmatrix.sync.aligned.m8n8.x2.shared.b16 {%0,%1}, [%2];"
                 : "=r"(r0), "=r"(r1) : "r"(addr));
}
__device__ __forceinline__ void ldsm_x2t(unsigned addr, unsigned& r0, unsigned& r1) {
    asm volatile("ldmatrix.sync.aligned.m8n8.x2.trans.shared.b16 {%0,%1}, [%2];"
                 : "=r"(r0), "=r"(r1) : "r"(addr));
}
__device__ __forceinline__ void mma16816(float* c, const unsigned* a,
                                         unsigned b0, unsigned b1) {
    asm volatile("mma.sync.aligned.m16n8k16.row.col.f32.bf16.bf16.f32 "
                 "{%0,%1,%2,%3}, {%4,%5,%6,%7}, {%8,%9}, {%0,%1,%2,%3};"
                 : "+f"(c[0]), "+f"(c[1]), "+f"(c[2]), "+f"(c[3])
                 : "r"(a[0]), "r"(a[1]), "r"(a[2]), "r"(a[3]), "r"(b0), "r"(b1));
}
__device__ __forceinline__ unsigned pack_bf16(float lo, float hi) {
    unsigned d;
    asm("cvt.rn.bf16x2.f32 %0, %1, %2;" : "=r"(d) : "f"(hi), "f"(lo));
    return d;
}
__device__ __forceinline__ void cpasync16(unsigned dst, const void* src) {
    asm volatile("cp.async.cg.shared.global [%0], [%1], 16;" :: "r"(dst), "l"(src));
}
__device__ __forceinline__ void cp_commit() {
    asm volatile("cp.async.commit_group;");
}
template<int N>
__device__ __forceinline__ void cp_wait() {
    asm volatile("cp.async.wait_group %0;" :: "n"(N));
}

// ---------------------------------------------------------------------------
// Kernel 1: fused LayerNorm + projection GEMM -> bf16 output (pre-scaled).
// x in CHW layout [(slab*128 + d)*HW + p], row = slab*HW + p.
// ---------------------------------------------------------------------------
__global__ __launch_bounds__(256)
void gemm_ln_kernel(const float* __restrict__ x,
                    const float* __restrict__ g, const float* __restrict__ bt,
                    const float* __restrict__ W, const float* __restrict__ bias,
                    __nv_bfloat16* __restrict__ C, int HW, float outScale) {
    __shared__ float As[64 * 132];
    __shared__ __align__(16) float Bs[16 * 68];
    __shared__ float rowm[64], rowr[64];

    const int tid = threadIdx.x;
    const int tx  = tid & 15;
    const int ty  = tid >> 4;
    const int m0  = blockIdx.y * 64;
    const int n0  = blockIdx.x * 64;

    // stage raw A tile: coalesced in p
    {
        const int rr = tid & 63;
        int slab = m0 / HW;
        int p    = m0 - slab * HW + rr;
        if (p >= HW) { p -= HW; slab++; }
        const float* src = x + ((size_t)slab * DIMC) * HW + p;
        const int dbase = tid >> 6;
        #pragma unroll
        for (int i = 0; i < 32; ++i) {
            int d = dbase + i * 4;
            As[rr * 132 + d] = src[(size_t)d * HW];
        }
    }
    __syncthreads();

    // row stats: 4 threads per row
    {
        const int r  = tid >> 2;
        const int qd = tid & 3;
        float s = 0.f, ss = 0.f;
        #pragma unroll
        for (int j = 0; j < 32; ++j) {
            float v = As[r * 132 + qd + 4 * j];
            s += v; ss += v * v;
        }
        s  += __shfl_xor_sync(0xffffffffu, s, 1);
        ss += __shfl_xor_sync(0xffffffffu, ss, 1);
        s  += __shfl_xor_sync(0xffffffffu, s, 2);
        ss += __shfl_xor_sync(0xffffffffu, ss, 2);
        if (qd == 0) {
            float mean = s * (1.f / 128.f);
            rowm[r] = mean;
            rowr[r] = rsqrtf(ss * (1.f / 128.f) - mean * mean + 1e-5f);
        }
    }
    __syncthreads();

    // normalize in place
    {
        const int rr = tid & 63;
        const int dbase = tid >> 6;
        float mean = rowm[rr], rstd = rowr[rr];
        #pragma unroll
        for (int i = 0; i < 32; ++i) {
            int d = dbase + i * 4;
            float v = As[rr * 132 + d];
            As[rr * 132 + d] = (v - mean) * rstd * g[d] + bt[d];
        }
    }
    __syncthreads();

    float acc[4][4] = {};
    for (int kt = 0; kt < 128; kt += 16) {
        #pragma unroll
        for (int e = tid; e < 16 * 64; e += 256) {
            int k = e & 15, n = e >> 4;
            Bs[k * 68 + n] = W[(n0 + n) * 128 + kt + k];
        }
        __syncthreads();
        #pragma unroll
        for (int kk = 0; kk < 16; ++kk) {
            float a0 = As[(ty * 4 + 0) * 132 + kt + kk];
            float a1 = As[(ty * 4 + 1) * 132 + kt + kk];
            float a2 = As[(ty * 4 + 2) * 132 + kt + kk];
            float a3 = As[(ty * 4 + 3) * 132 + kt + kk];
            float4 bv = *reinterpret_cast<const float4*>(&Bs[kk * 68 + tx * 4]);
            acc[0][0] += a0 * bv.x; acc[0][1] += a0 * bv.y; acc[0][2] += a0 * bv.z; acc[0][3] += a0 * bv.w;
            acc[1][0] += a1 * bv.x; acc[1][1] += a1 * bv.y; acc[1][2] += a1 * bv.z; acc[1][3] += a1 * bv.w;
            acc[2][0] += a2 * bv.x; acc[2][1] += a2 * bv.y; acc[2][2] += a2 * bv.z; acc[2][3] += a2 * bv.w;
            acc[3][0] += a3 * bv.x; acc[3][1] += a3 * bv.y; acc[3][2] += a3 * bv.z; acc[3][3] += a3 * bv.w;
        }
        __syncthreads();
    }

    #pragma unroll
    for (int i = 0; i < 4; ++i) {
        int row = m0 + ty * 4 + i;
        #pragma unroll
        for (int j = 0; j < 4; ++j) {
            int col = n0 + tx * 4 + j;
            C[(size_t)row * 128 + col] =
                __float2bfloat16((acc[i][j] + bias[col]) * outScale);
        }
    }
}

// ---------------------------------------------------------------------------
// Kernel 2: plain fp32 GEMM + bias (+ optional exact GELU).
// ---------------------------------------------------------------------------
template<bool GELU>
__global__ __launch_bounds__(256)
void gemm_bias_kernel(const float* __restrict__ A, const float* __restrict__ W,
                      const float* __restrict__ bias, float* __restrict__ C,
                      int M, int N, int K) {
    __shared__ __align__(16) float As[64 * 17];
    __shared__ __align__(16) float Bs[16 * 68];

    const int tid = threadIdx.x;
    const int tx  = tid & 15;
    const int ty  = tid >> 4;
    const int m0  = blockIdx.y * 64;
    const int n0  = blockIdx.x * 64;

    float acc[4][4] = {};

    for (int kt = 0; kt < K; kt += 16) {
        #pragma unroll
        for (int e = tid; e < 64 * 16; e += 256) {
            int r = e >> 4, k = e & 15;
            As[r * 17 + k] = A[(m0 + r) * K + kt + k];
        }
        #pragma unroll
        for (int e = tid; e < 16 * 64; e += 256) {
            int k = e & 15, n = e >> 4;
            Bs[k * 68 + n] = W[(n0 + n) * K + kt + k];
        }
        __syncthreads();
        #pragma unroll
        for (int kk = 0; kk < 16; ++kk) {
            float a0 = As[(ty * 4 + 0) * 17 + kk];
            float a1 = As[(ty * 4 + 1) * 17 + kk];
            float a2 = As[(ty * 4 + 2) * 17 + kk];
            float a3 = As[(ty * 4 + 3) * 17 + kk];
            float4 bv = *reinterpret_cast<const float4*>(&Bs[kk * 68 + tx * 4]);
            acc[0][0] += a0 * bv.x; acc[0][1] += a0 * bv.y; acc[0][2] += a0 * bv.z; acc[0][3] += a0 * bv.w;
            acc[1][0] += a1 * bv.x; acc[1][1] += a1 * bv.y; acc[1][2] += a1 * bv.z; acc[1][3] += a1 * bv.w;
            acc[2][0] += a2 * bv.x; acc[2][1] += a2 * bv.y; acc[2][2] += a2 * bv.z; acc[2][3] += a2 * bv.w;
            acc[3][0] += a3 * bv.x; acc[3][1] += a3 * bv.y; acc[3][2] += a3 * bv.z; acc[3][3] += a3 * bv.w;
        }
        __syncthreads();
    }

    #pragma unroll
    for (int i = 0; i < 4; ++i) {
        int row = m0 + ty * 4 + i;
        #pragma unroll
        for (int j = 0; j < 4; ++j) {
            int col = n0 + tx * 4 + j;
            float v = acc[i][j] + bias[col];
            if (GELU) v = 0.5f * v * (1.f + erff(v * 0.70710678118654752f));
            C[row * N + col] = v;
        }
    }
}

// ---------------------------------------------------------------------------
// Kernel 3: tensor-core flash attention partial (one view per block).
// Block = 64 queries x (head,batch,view). 128 threads (4 warps x 16 q).
// Q pre-scaled by ATTN_SCALE (in qp). Writes unnormalized O + (m,l).
// ---------------------------------------------------------------------------
__global__ __launch_bounds__(128)
void attn_mma_kernel(const __nv_bfloat16* __restrict__ qp,
                     const __nv_bfloat16* __restrict__ kp,
                     const __nv_bfloat16* __restrict__ vp,
                     float* __restrict__ pO, float* __restrict__ pml) {
    const int qt = blockIdx.x;           // 0..15
    const int mb = blockIdx.y;           // b*4 + m, 0..7
    const int nn = blockIdx.z;           // view 0..5
    const int b  = mb >> 2, m = mb & 3;
    const int tid = threadIdx.x;
    const int w = tid >> 5, lane = tid & 31;

    __shared__ __align__(16) __nv_bfloat16 Qs[AQT * KVSTR];
    __shared__ __align__(16) __nv_bfloat16 Ks[2][AKC * KVSTR];
    __shared__ __align__(16) __nv_bfloat16 Vs[2][AKC * KVSTR];

    // ---- stage Q: 64 rows x 32 bf16 (256 uint4) ----
    {
        const __nv_bfloat16* qbase =
            qp + ((size_t)(b * NVIEW + nn) * HWQ + qt * AQT) * DIMC + m * DH;
        #pragma unroll
        for (int r = 0; r < 2; ++r) {
            int e = tid + r * 128;
            int row = e >> 2, seg = e & 3;
            *reinterpret_cast<uint4*>(&Qs[row * KVSTR + seg * 8]) =
                *reinterpret_cast<const uint4*>(&qbase[(size_t)row * DIMC + seg * 8]);
        }
    }
    __syncthreads();

    // ---- Q A-fragments (2 k-steps, resident all kernel) ----
    unsigned qa[2][4];
    {
        int row = 16 * w + (lane & 7) + (lane & 8);
        #pragma unroll
        for (int ks = 0; ks < 2; ++ks) {
            int col = 16 * ks + ((lane >> 4) & 1) * 8;
            unsigned addr = (unsigned)__cvta_generic_to_shared(&Qs[row * KVSTR + col]);
            ldsm_x4(addr, qa[ks]);
        }
    }

    // K/V staging decomposition: 384 uint4 entries, 3 per thread
    int srow[3], sseg[3], sarr[3];
    #pragma unroll
    for (int r = 0; r < 3; ++r) {
        int e = tid + r * 128;           // 0..383
        sarr[r] = (e >= 192);
        int idx = e - (sarr[r] ? 192 : 0);
        srow[r] = idx >> 2;              // 0..47
        sseg[r] = idx & 3;               // 16B segment
    }
    const __nv_bfloat16* kb0 =
        kp + ((size_t)(b * NVIEW + nn) * HWK) * DIMC + m * DH;
    const __nv_bfloat16* vb0 =
        vp + ((size_t)(b * NVIEW + nn) * HWK) * DIMC + m * DH;

    auto stage = [&](int c, int buf) {
        size_t base = (size_t)(c * AKC) * DIMC;
        #pragma unroll
        for (int r = 0; r < 3; ++r) {
            const __nv_bfloat16* src =
                (sarr[r] ? vb0 : kb0) + base + (size_t)srow[r] * DIMC + sseg[r] * 8;
            __nv_bfloat16* dstp =
                (sarr[r] ? Vs[buf] : Ks[buf]) + srow[r] * KVSTR + sseg[r] * 8;
            cpasync16((unsigned)__cvta_generic_to_shared(dstp), src);
        }
        cp_commit();
    };

    stage(0, 0);

    float m0r = -INFINITY, m1r = -INFINITY, l0r = 0.f, l1r = 0.f;
    float oc[4][4] = {};  // 4 d-tiles x 4 accum

    for (int ci = 0; ci < NCH; ++ci) {
        const int cur = ci & 1;
        if (ci + 1 < NCH) { stage(ci + 1, cur ^ 1); cp_wait<1>(); }
        else              { cp_wait<0>(); }
        __syncthreads();

        // ---- S = Q K^T : 6 n-tiles, 2 k-steps each ----
        float sc[6][4];
        #pragma unroll
        for (int nt = 0; nt < 6; ++nt) {
            sc[nt][0] = sc[nt][1] = sc[nt][2] = sc[nt][3] = 0.f;
            int krow = nt * 8 + (lane & 7);
            int kcol = ((lane >> 3) & 1) * 8;
            unsigned a0 = (unsigned)__cvta_generic_to_shared(
                &Ks[cur][krow * KVSTR + kcol]);
            unsigned a1 = (unsigned)__cvta_generic_to_shared(
                &Ks[cur][krow * KVSTR + kcol + 16]);
            unsigned b0, b1, b2, b3;
            ldsm_x2(a0, b0, b1);
            ldsm_x2(a1, b2, b3);
            mma16816(sc[nt], qa[0], b0, b1);
            mma16816(sc[nt], qa[1], b2, b3);
        }

        // ---- online softmax in fragments ----
        {
            float mx0 = sc[0][0], mx1 = sc[0][2];
            #pragma unroll
            for (int nt = 0; nt < 6; ++nt) {
                mx0 = fmaxf(mx0, fmaxf(sc[nt][0], sc[nt][1]));
                mx1 = fmaxf(mx1, fmaxf(sc[nt][2], sc[nt][3]));
            }
            mx0 = fmaxf(mx0, __shfl_xor_sync(0xffffffffu, mx0, 1));
            mx0 = fmaxf(mx0, __shfl_xor_sync(0xffffffffu, mx0, 2));
            mx1 = fmaxf(mx1, __shfl_xor_sync(0xffffffffu, mx1, 1));
            mx1 = fmaxf(mx1, __shfl_xor_sync(0xffffffffu, mx1, 2));
            float nm0 = fmaxf(m0r, mx0), nm1 = fmaxf(m1r, mx1);
            float al0 = __expf(m0r - nm0), al1 = __expf(m1r - nm1);
            float s0 = 0.f, s1 = 0.f;
            #pragma unroll
            for (int nt = 0; nt < 6; ++nt) {
                sc[nt][0] = __expf(sc[nt][0] - nm0);
                sc[nt][1] = __expf(sc[nt][1] - nm0);
                sc[nt][2] = __expf(sc[nt][2] - nm1);
                sc[nt][3] = __expf(sc[nt][3] - nm1);
                s0 += sc[nt][0] + sc[nt][1];
                s1 += sc[nt][2] + sc[nt][3];
            }
            s0 += __shfl_xor_sync(0xffffffffu, s0, 1);
            s0 += __shfl_xor_sync(0xffffffffu, s0, 2);
            s1 += __shfl_xor_sync(0xffffffffu, s1, 1);
            s1 += __shfl_xor_sync(0xffffffffu, s1, 2);
            l0r = l0r * al0 + s0;  l1r = l1r * al1 + s1;
            m0r = nm0;             m1r = nm1;
            #pragma unroll
            for (int dt = 0; dt < 4; ++dt) {
                oc[dt][0] *= al0; oc[dt][1] *= al0;
                oc[dt][2] *= al1; oc[dt][3] *= al1;
            }
        }

        // ---- O += P V : 3 k-steps x 4 d-tiles ----
        #pragma unroll
        for (int t = 0; t < 3; ++t) {
            unsigned pa[4];
            pa[0] = pack_bf16(sc[2 * t][0], sc[2 * t][1]);
            pa[1] = pack_bf16(sc[2 * t][2], sc[2 * t][3]);
            pa[2] = pack_bf16(sc[2 * t + 1][0], sc[2 * t + 1][1]);
            pa[3] = pack_bf16(sc[2 * t + 1][2], sc[2 * t + 1][3]);
            int vrow = 16 * t + (lane & 15);
            #pragma unroll
            for (int dt = 0; dt < 4; ++dt) {
                unsigned addr = (unsigned)__cvta_generic_to_shared(
                    &Vs[cur][vrow * KVSTR + 8 * dt]);
                unsigned v0, v1;
                ldsm_x2t(addr, v0, v1);
                mma16816(oc[dt], pa, v0, v1);
            }
        }
        __syncthreads();
    }

    // ---- write partials ----
    const int PB = (nn * 8 + mb) * 16 + qt;
    float* po = pO + (size_t)PB * AQT * DH;
    const int r0 = 16 * w + (lane >> 2);
    #pragma unroll
    for (int dt = 0; dt < 4; ++dt) {
        int c0 = dt * 8 + 2 * (lane & 3);
        *reinterpret_cast<float2*>(&po[r0 * DH + c0])       = make_float2(oc[dt][0], oc[dt][1]);
        *reinterpret_cast<float2*>(&po[(r0 + 8) * DH + c0]) = make_float2(oc[dt][2], oc[dt][3]);
    }
    if ((lane & 3) == 0) {
        float* ml = pml + ((size_t)PB * AQT) * 2;
        ml[r0 * 2 + 0] = m0r;       ml[r0 * 2 + 1] = l0r;
        ml[(r0 + 8) * 2 + 0] = m1r; ml[(r0 + 8) * 2 + 1] = l1r;
    }
}

// ---------------------------------------------------------------------------
// Kernel 4: merge 6 per-view partials -> normalized aout (fp32).
// Thread per (mb, qt, row, d): 8192 rows x 32 dims.
// ---------------------------------------------------------------------------
__global__ void attn_merge_kernel(const float* __restrict__ pO,
                                  const float* __restrict__ pml,
                                  float* __restrict__ aout) {
    int t = blockIdx.x * 256 + threadIdx.x;   // 0..262143
    int d   = t & 31;
    int r   = (t >> 5) & 63;
    int qt  = (t >> 11) & 15;
    int mb  = t >> 15;                        // 0..7
    int b = mb >> 2, m = mb & 3;

    float mv[NVIEW], lv[NVIEW];
    float M = -INFINITY;
    #pragma unroll
    for (int nn = 0; nn < NVIEW; ++nn) {
        int PB = (nn * 8 + mb) * 16 + qt;
        mv[nn] = pml[((size_t)PB * AQT + r) * 2 + 0];
        lv[nn] = pml[((size_t)PB * AQT + r) * 2 + 1];
        M = fmaxf(M, mv[nn]);
    }
    float L = 0.f, O = 0.f;
    #pragma unroll
    for (int nn = 0; nn < NVIEW; ++nn) {
        int PB = (nn * 8 + mb) * 16 + qt;
        float e = __expf(mv[nn] - M);
        L += lv[nn] * e;
        O += pO[((size_t)PB * AQT + r) * DH + d] * e;
    }
    aout[((size_t)b * HWQ + qt * AQT + r) * INNER + m * DH + d] = O / L;
}

// ---------------------------------------------------------------------------
// Kernel 5: z = LN1(proj_out + skip(CHW)).
// ---------------------------------------------------------------------------
__global__ void skip_ln_kernel(const float* __restrict__ z1,
                               const float* __restrict__ skip,
                               const float* __restrict__ g,
                               const float* __restrict__ bt,
                               float* __restrict__ zn) {
    int row = blockIdx.x;
    int b = row >> 10, p = row & 1023;
    int d = threadIdx.x;
    float v = z1[row * DIMC + d] + skip[(b * DIMC + d) * HWQ + p];

    float s = v, ss = v * v;
    #pragma unroll
    for (int o = 16; o; o >>= 1) {
        s  += __shfl_xor_sync(0xffffffffu, s,  o);
        ss += __shfl_xor_sync(0xffffffffu, ss, o);
    }
    __shared__ float sh[8];
    int w = d >> 5, l = d & 31;
    if (l == 0) { sh[w] = s; sh[4 + w] = ss; }
    __syncthreads();
    s  = sh[0] + sh[1] + sh[2] + sh[3];
    ss = sh[4] + sh[5] + sh[6] + sh[7];
    float mean = s * (1.f / 128.f);
    float rstd = rsqrtf(ss * (1.f / 128.f) - mean * mean + 1e-5f);
    zn[row * DIMC + d] = (v - mean) * rstd * g[d] + bt[d];
}

// ---------------------------------------------------------------------------
// Kernel 6: out(CHW) = LN2(zn + mlp_out).
// ---------------------------------------------------------------------------
__global__ void final_ln_kernel(const float* __restrict__ zn,
                                const float* __restrict__ m2,
                                const float* __restrict__ g,
                                const float* __restrict__ bt,
                                float* __restrict__ out) {
    int row = blockIdx.x;
    int b = row >> 10, p = row & 1023;
    int d = threadIdx.x;
    float v = zn[row * DIMC + d] + m2[row * DIMC + d];

    float s = v, ss = v * v;
    #pragma unroll
    for (int o = 16; o; o >>= 1) {
        s  += __shfl_xor_sync(0xffffffffu, s,  o);
        ss += __shfl_xor_sync(0xffffffffu, ss, o);
    }
    __shared__ float sh[8];
    int w = d >> 5, l = d & 31;
    if (l == 0) { sh[w] = s; sh[4 + w] = ss; }
    __syncthreads();
    s  = sh[0] + sh[1] + sh[2] + sh[3];
    ss = sh[4] + sh[5] + sh[6] + sh[7];
    float mean = s * (1.f / 128.f);
    float rstd = rsqrtf(ss * (1.f / 128.f) - mean * mean + 1e-5f);
    out[(b * DIMC + d) * HWQ + p] = (v - mean) * rstd * g[d] + bt[d];
}

// ---------------------------------------------------------------------------
// Launcher
// ---------------------------------------------------------------------------
extern "C" void kernel_launch(void* const* d_in, const int* in_sizes, int n_in,
                              void* d_out, int out_size) {
    const float* q     = (const float*)d_in[0];
    const float* k     = (const float*)d_in[1];
    const float* v     = (const float*)d_in[2];
    const float* skip  = (const float*)d_in[3];
    const float* lnq_g = (const float*)d_in[4];
    const float* lnq_b = (const float*)d_in[5];
    const float* Wq    = (const float*)d_in[6];
    const float* bq    = (const float*)d_in[7];
    const float* lnk_g = (const float*)d_in[8];
    const float* lnk_b = (const float*)d_in[9];
    const float* Wk    = (const float*)d_in[10];
    const float* bk    = (const float*)d_in[11];
    const float* lnv_g = (const float*)d_in[12];
    const float* lnv_b = (const float*)d_in[13];
    const float* Wv    = (const float*)d_in[14];
    const float* bv    = (const float*)d_in[15];
    const float* Wp    = (const float*)d_in[16];
    const float* bp    = (const float*)d_in[17];
    const float* ln1_g = (const float*)d_in[18];
    const float* ln1_b = (const float*)d_in[19];
    const float* W1    = (const float*)d_in[20];
    const float* b1    = (const float*)d_in[21];
    const float* W2    = (const float*)d_in[22];
    const float* b2    = (const float*)d_in[23];
    const float* ln2_g = (const float*)d_in[24];
    const float* ln2_b = (const float*)d_in[25];
    float* out = (float*)d_out;

    __nv_bfloat16 *qp, *kp, *vp;
    float *pO, *pml, *aout, *z1, *zn, *hh, *m2;
    cudaGetSymbolAddress((void**)&qp,   d_qp);
    cudaGetSymbolAddress((void**)&kp,   d_kp);
    cudaGetSymbolAddress((void**)&vp,   d_vp);
    cudaGetSymbolAddress((void**)&pO,   d_pO);
    cudaGetSymbolAddress((void**)&pml,  d_pml);
    cudaGetSymbolAddress((void**)&aout, d_aout);
    cudaGetSymbolAddress((void**)&z1,   d_z1);
    cudaGetSymbolAddress((void**)&zn,   d_zn);
    cudaGetSymbolAddress((void**)&hh,   d_hh);
    cudaGetSymbolAddress((void**)&m2,   d_m2);

    // 1. Fused LN + projections -> bf16 (Q pre-scaled by 1/sqrt(dh))
    gemm_ln_kernel<<<dim3(2, ROWS_Q / 64), 256>>>(q, lnq_g, lnq_b, Wq, bq, qp, HWQ, ATTN_SCALE);
    gemm_ln_kernel<<<dim3(2, ROWS_K / 64), 256>>>(k, lnk_g, lnk_b, Wk, bk, kp, HWK, 1.0f);
    gemm_ln_kernel<<<dim3(2, ROWS_K / 64), 256>>>(v, lnv_g, lnv_b, Wv, bv, vp, HWK, 1.0f);

    // 2. Tensor-core attention partials (per view) + merge (joint softmax)
    attn_mma_kernel<<<dim3(16, 8, NVIEW), 128>>>(qp, kp, vp, pO, pml);
    attn_merge_kernel<<<1024, 256>>>(pO, pml, aout);

    // 3. Output projection + skip + LN1
    gemm_bias_kernel<false><<<dim3(2, ROWS_Z / 64), 256>>>(aout, Wp, bp, z1, ROWS_Z, 128, 128);
    skip_ln_kernel<<<ROWS_Z, 128>>>(z1, skip, ln1_g, ln1_b, zn);

    // 4. MLP (GELU exact) + residual + LN2 + NCHW output
    gemm_bias_kernel<true ><<<dim3(4, ROWS_Z / 64), 256>>>(zn, W1, b1, hh, ROWS_Z, 256, 128);
    gemm_bias_kernel<false><<<dim3(2, ROWS_Z / 64), 256>>>(hh, W2, b2, m2, ROWS_Z, 128, 256);
    final_ln_kernel<<<ROWS_Z, 128>>>(zn, m2, ln2_g, ln2_b, out);
}